// round 9
// baseline (speedup 1.0000x reference)
#include <cuda_runtime.h>
#include <cstdint>
#include <cstddef>

#define TSTEPS 16384
#define BATCH  32
#define HID    96
#define GATES  384
#define NCOMP  768            // 24 compute warps: 2 threads per gate-row
#define NTH    800            // + 1 aux output warp
#define SMEM_FLOATS (TSTEPS + 2 * HID + 8)
#define SMEM_BYTES  (SMEM_FLOATS * sizeof(float))

__device__ __forceinline__ float tanh_fast(float x) {
    float y;
    asm("tanh.approx.f32 %0, %1;" : "=f"(y) : "f"(x));   // MUFU.TANH
    return y;
}

__global__ void __launch_bounds__(NTH, 1)
lstm_persist(const float* __restrict__ x,
             const float* __restrict__ w_ih,
             const float* __restrict__ w_hh,
             const float* __restrict__ b_ih,
             const float* __restrict__ b_hh,
             const float* __restrict__ fc_w,
             const float* __restrict__ fc_b,
             float* __restrict__ out)
{
    extern __shared__ float smem[];
    float* xs = smem;                    // [TSTEPS] x column for this batch elem
    float* hb = smem + TSTEPS;           // [2][HID] double-buffered hidden state

    const int tid = threadIdx.x;
    const int b   = blockIdx.x;          // one CTA / batch element / SM

    // Stage x[:, b] into shared (one-time).
    for (int t = tid; t < TSTEPS; t += NTH)
        xs[t] = x[(size_t)t * BATCH + b];

    // ---- per-thread persistent state ----
    // Thread map (tid < 768):  unit = (warp*4) + bits[4:3],  gate q = bits[2:1],
    // half s = bit 0.  Row = q*96 + unit.  This thread covers h-cols [48s, 48s+48).
    unsigned long long w2[24];           // 48 weights as 24 packed f32x2
    float wih = 0.f, bias = 0.f, c = 0.f;
    float act_a = 0.5f, act_s = 0.5f, act_b = 0.5f;   // sigmoid = 0.5*tanh(0.5x)+0.5
    float fw0 = 0.f, fw1 = 0.f, fw2 = 0.f, fcb = 0.f;
    int   unit = 0, half = 0;

    if (tid < NCOMP) {
        unit = ((tid >> 5) << 2) + ((tid >> 3) & 3);
        const int q = (tid >> 1) & 3;    // 0=i,1=f,2=g,3=o
        half = tid & 1;
        const int row = q * HID + unit;
        const unsigned long long* wrow =
            reinterpret_cast<const unsigned long long*>(w_hh + row * HID + 48 * half);
        #pragma unroll
        for (int k = 0; k < 24; ++k) w2[k] = wrow[k];
        wih  = __ldg(w_ih + row);
        bias = __ldg(b_ih + row) + __ldg(b_hh + row);
        if (q == 2) { act_a = 1.f; act_s = 1.f; act_b = 0.f; }  // g-gate: plain tanh
    } else {
        const int l = tid - NCOMP;       // aux warp: fc weights, 3 per lane
        fw0 = fc_w[l]; fw1 = fc_w[l + 32]; fw2 = fc_w[l + 64];
        fcb = fc_b[0];
    }
    if (tid < HID) hb[tid] = 0.f;        // h0 = 0; c0 = 0 in regs
    __syncthreads();

    float* h_rd = hb;                    // h_{t-1}
    float* h_wr = hb + HID;              // h_t

    #pragma unroll 1
    for (int t = 0; t < TSTEPS; ++t) {
        if (tid < NCOMP) {
            // gx off the critical tail: independent of h
            const float gx = fmaf(xs[t], wih, bias);

            // ---- half-dot over 48 cols via packed FFMA2, 2 chains ----
            const ulonglong2* hv =
                reinterpret_cast<const ulonglong2*>(h_rd + 48 * half);
            unsigned long long a0 = 0ull, a1 = 0ull;
            #pragma unroll
            for (int k = 0; k < 6; ++k) {
                ulonglong2 p = hv[2 * k];
                ulonglong2 r = hv[2 * k + 1];
                asm("fma.rn.f32x2 %0, %1, %2, %0;" : "+l"(a0) : "l"(w2[4*k+0]), "l"(p.x));
                asm("fma.rn.f32x2 %0, %1, %2, %0;" : "+l"(a1) : "l"(w2[4*k+1]), "l"(p.y));
                asm("fma.rn.f32x2 %0, %1, %2, %0;" : "+l"(a0) : "l"(w2[4*k+2]), "l"(r.x));
                asm("fma.rn.f32x2 %0, %1, %2, %0;" : "+l"(a1) : "l"(w2[4*k+3]), "l"(r.y));
            }
            asm("add.rn.f32x2 %0, %0, %1;" : "+l"(a0) : "l"(a1));
            unsigned lo, hi;
            asm("mov.b64 {%0,%1}, %2;" : "=r"(lo), "=r"(hi) : "l"(a0));
            float part = __uint_as_float(lo) + __uint_as_float(hi);

            // combine the two halves (lanes s=0/1 of this row)
            const unsigned m = 0xffffffffu;
            float dot = part + __shfl_xor_sync(m, part, 1);

            // activation (uniform MUFU.TANH path)
            float g   = dot + gx;
            float act = fmaf(tanh_fast(g * act_a), act_s, act_b);

            // ---- cell update: unit's 4 gates live in 8 consecutive lanes ----
            float gi = __shfl_sync(m, act, 0, 8);
            float gf = __shfl_sync(m, act, 2, 8);
            float gg = __shfl_sync(m, act, 4, 8);
            float go = __shfl_sync(m, act, 6, 8);
            c = fmaf(gf, c, gi * gg);            // replicated across the octet
            float h = go * tanh_fast(c);
            if ((tid & 7) == 0) h_wr[unit] = h;  // octet leader publishes
        } else if (t > 0) {
            // aux warp: out[t-1] = fc_w . h_{t-1} + fc_b + x[t-1]
            const int l = tid - NCOMP;
            float p = fw0 * h_rd[l] + fw1 * h_rd[l + 32] + fw2 * h_rd[l + 64];
            #pragma unroll
            for (int off = 16; off > 0; off >>= 1)
                p += __shfl_xor_sync(0xffffffffu, p, off);
            if (l == 0)
                out[(size_t)(t - 1) * BATCH + b] = p + fcb + xs[t - 1];
        }

        __syncthreads();                 // h_t published; h_rd free for reuse
        float* tmp = h_rd; h_rd = h_wr; h_wr = tmp;
    }

    // Final output: h_{T-1} is in the read buffer after the last swap.
    if (tid >= NCOMP) {
        const int l = tid - NCOMP;
        float p = fw0 * h_rd[l] + fw1 * h_rd[l + 32] + fw2 * h_rd[l + 64];
        #pragma unroll
        for (int off = 16; off > 0; off >>= 1)
            p += __shfl_xor_sync(0xffffffffu, p, off);
        if (l == 0)
            out[(size_t)(TSTEPS - 1) * BATCH + b] = p + fcb + xs[TSTEPS - 1];
    }
}

extern "C" void kernel_launch(void* const* d_in, const int* in_sizes, int n_in,
                              void* d_out, int out_size)
{
    const float* x    = (const float*)d_in[0];
    const float* w_ih = (const float*)d_in[1];
    const float* w_hh = (const float*)d_in[2];
    const float* b_ih = (const float*)d_in[3];
    const float* b_hh = (const float*)d_in[4];
    const float* fc_w = (const float*)d_in[5];
    const float* fc_b = (const float*)d_in[6];
    float* out = (float*)d_out;

    cudaFuncSetAttribute(lstm_persist,
                         cudaFuncAttributeMaxDynamicSharedMemorySize,
                         (int)SMEM_BYTES);
    lstm_persist<<<BATCH, NTH, SMEM_BYTES>>>(x, w_ih, w_hh, b_ih, b_hh,
                                             fc_w, fc_b, out);
}